// round 13
// baseline (speedup 1.0000x reference)
#include <cuda_runtime.h>
#include <cuda_bf16.h>
#include <math.h>

// Shapes: B=32, H=8, J=8192, K=128
#define B_ 32
#define H_ 8
#define J_ 8192
#define K_ 128
#define EPSV 1e-6f

#define CTA_THREADS 128
#define ROWS 128            // j rows per CTA (1 per thread)
#define WROWS 32            // j rows per warp
#define NCHUNK 64           // j chunks per batch = J_/ROWS
#define KC 16               // k per stage (64B per row per stage)
#define NKC 8               // stages = K_/KC
#define PAD 20              // floats per staged row; conflict-free LDS.128
#define WBUF (WROWS * PAD)  // 640 floats = 2.5 KB per warp buffer
// total dyn smem: 4 warps * 2 buffers * 2.5 KB = 20 KB

typedef unsigned long long ull;

// scratch: exp(sharp - chunk_max), 32*8*8192 f32 = 8 MB
__device__ float g_scratch[B_ * H_ * J_];
// per-(b,h,chunk) partials {max, sumexp}
__device__ float2 g_part[B_ * H_ * NCHUNK];
// per-(b,h,chunk) final softmax scale
__device__ float g_scale[B_ * H_ * NCHUNK];

#define FMA2(d, a, b, c) asm("fma.rn.f32x2 %0, %1, %2, %3;" : "=l"(d) : "l"(a), "l"(b), "l"(c))
#define MUL2(d, a, b)    asm("mul.rn.f32x2 %0, %1, %2;"     : "=l"(d) : "l"(a), "l"(b))
#define PACK2(d, lo, hi) asm("mov.b64 %0, {%1, %2};" : "=l"(d) : "f"(lo), "f"(hi))
#define UNPACK2(lo, hi, s) asm("mov.b64 {%0, %1}, %2;" : "=f"(lo), "=f"(hi) : "l"(s))

__device__ __forceinline__ void cp_async16(void* smem_dst, const void* gsrc) {
    unsigned saddr = (unsigned)__cvta_generic_to_shared(smem_dst);
    asm volatile("cp.async.cg.shared.global [%0], [%1], 16;" :: "r"(saddr), "l"(gsrc));
}

__global__ void __launch_bounds__(CTA_THREADS, 5)
cw_main_kernel(const float* __restrict__ memory,
               const float* __restrict__ keys,
               const float* __restrict__ strengths,
               const float* __restrict__ mask)
{
    extern __shared__ float sdata[];   // 4 warps * 2 * WBUF

    const int b = blockIdx.y;
    const int chunk = blockIdx.x;      // NCHUNK chunks of ROWS j
    const int tid = threadIdx.x;       // 128 threads
    const int lane = tid & 31;
    const int wid = tid >> 5;          // 4 warps

    __shared__ __align__(16) float s_w[K_ * H_];   // [k][h]
    __shared__ __align__(16) float s_m2[K_ * H_];  // [k][h]
    __shared__ float s_kn[H_];
    __shared__ float s_sps[H_];
    __shared__ float s_redA[4][8];
    __shared__ float s_redB[4][8];

    // ---- coefficient prep ----
    const float* mk = mask + b * (H_ * K_);
    const float* ky = keys + b * (H_ * K_);
    for (int i = tid; i < H_ * K_; i += CTA_THREADS) {
        int h = i >> 7;
        int k = i & 127;
        float m = mk[i];
        float kv = ky[i];
        float m2 = m * m;
        s_w[k * 8 + h]  = m2 * kv;
        s_m2[k * 8 + h] = m2;
    }
    // keys_norm: warp w handles heads w and w+4
    #pragma unroll
    for (int hh = 0; hh < 2; ++hh) {
        int h = wid + hh * 4;
        float s = 0.f;
        #pragma unroll
        for (int kk = 0; kk < 4; ++kk) {
            int k = lane + kk * 32;
            float v = mk[h * K_ + k] * ky[h * K_ + k];
            s += v * v;
        }
        #pragma unroll
        for (int o = 16; o; o >>= 1) s += __shfl_xor_sync(0xffffffffu, s, o);
        if (lane == 0) s_kn[h] = sqrtf(s);
    }
    if (tid < H_) {
        float x = strengths[b * H_ + tid];
        s_sps[tid] = (x > 20.f) ? x : log1pf(__expf(x));
    }

    // ---- per-warp staging ----
    // warp wid owns global rows [chunk*ROWS + wid*32, +32) and its own smem region
    float* wbase = sdata + wid * (2 * WBUF);
    const float* gw = memory + ((size_t)b * J_ + (size_t)chunk * ROWS + (size_t)wid * WROWS) * K_;

    // per stage per warp: 32 rows x 16 floats = 128 x 16B ops; 4 per lane
    #define WSTAGE(kc, buf)                                                       \
        {                                                                         \
            float* dbase = wbase + (buf) * WBUF;                                  \
            _Pragma("unroll")                                                     \
            for (int it = 0; it < 4; ++it) {                                      \
                int idx = it * 32 + lane;                                         \
                int row = idx >> 2;                                               \
                int seg = idx & 3;                                                \
                cp_async16(dbase + row * PAD + seg * 4,                           \
                           gw + (size_t)row * K_ + (kc) * KC + seg * 4);          \
            }                                                                     \
            asm volatile("cp.async.commit_group;");                               \
        }

    WSTAGE(0, 0);
    __syncthreads();   // coefficients visible to all warps

    const ulonglong2* w128 = (const ulonglong2*)s_w;   // [kg*2 + p]: heads 4p..4p+3
    const ulonglong2* q128 = (const ulonglong2*)s_m2;

    ull accP[4], accN[4];
    #pragma unroll
    for (int hp = 0; hp < 4; ++hp) { accP[hp] = 0ull; accN[hp] = 0ull; }

    const int i0 = lane * (PAD / 4);   // this thread's row (float4 units)

    #pragma unroll
    for (int kc = 0; kc < NKC; ++kc) {
        if (kc < NKC - 1) {
            WSTAGE(kc + 1, (kc + 1) & 1);
            asm volatile("cp.async.wait_group 1;");
        } else {
            asm volatile("cp.async.wait_group 0;");
        }
        __syncwarp();   // cross-lane visibility of staged data

        const float4* dp = (const float4*)(wbase + (kc & 1) * WBUF);
        #pragma unroll
        for (int k4 = 0; k4 < 4; ++k4) {
            float4 d0 = dp[i0 + k4];
            float m0a[4] = {d0.x, d0.y, d0.z, d0.w};
            #pragma unroll
            for (int kk = 0; kk < 4; ++kk) {
                const int kg = kc * KC + k4 * 4 + kk;
                ulonglong2 wA = w128[kg * 2 + 0];   // heads 0-3
                ulonglong2 wB = w128[kg * 2 + 1];   // heads 4-7
                ulonglong2 qA = q128[kg * 2 + 0];
                ulonglong2 qB = q128[kg * 2 + 1];
                float m = m0a[kk];
                ull mm; PACK2(mm, m, m);
                ull ms; MUL2(ms, mm, mm);
                FMA2(accP[0], wA.x, mm, accP[0]);
                FMA2(accN[0], qA.x, ms, accN[0]);
                FMA2(accP[1], wA.y, mm, accP[1]);
                FMA2(accN[1], qA.y, ms, accN[1]);
                FMA2(accP[2], wB.x, mm, accP[2]);
                FMA2(accN[2], qB.x, ms, accN[2]);
                FMA2(accP[3], wB.y, mm, accP[3]);
                FMA2(accN[3], qB.y, ms, accN[3]);
            }
        }
        __syncwarp();   // all lanes done reading buffer before next overwrite
    }

    // ---- epilogue: sharp = proj/(kn*sqrt(nrm2)+eps) * sps ----
    float sharp[8];
    #pragma unroll
    for (int hp = 0; hp < 4; ++hp) {
        float p0, p1, n0, n1;
        UNPACK2(p0, p1, accP[hp]);
        UNPACK2(n0, n1, accN[hp]);
        const int h0 = hp * 2, h1 = hp * 2 + 1;
        sharp[h0] = p0 / (s_kn[h0] * sqrtf(n0) + EPSV) * s_sps[h0];
        sharp[h1] = p1 / (s_kn[h1] * sqrtf(n1) + EPSV) * s_sps[h1];
    }

    // ---- chunk-level softmax partials ----
    float cmax[8];
    #pragma unroll
    for (int h = 0; h < 8; ++h) {
        float t = sharp[h];
        #pragma unroll
        for (int o = 16; o; o >>= 1) t = fmaxf(t, __shfl_xor_sync(0xffffffffu, t, o));
        if (lane == 0) s_redA[wid][h] = t;
    }
    __syncthreads();
    #pragma unroll
    for (int h = 0; h < 8; ++h)
        cmax[h] = fmaxf(fmaxf(s_redA[0][h], s_redA[1][h]),
                        fmaxf(s_redA[2][h], s_redA[3][h]));

    float e[8];
    float csum[8];
    #pragma unroll
    for (int h = 0; h < 8; ++h) {
        e[h] = __expf(sharp[h] - cmax[h]);
        float t = e[h];
        #pragma unroll
        for (int o = 16; o; o >>= 1) t += __shfl_xor_sync(0xffffffffu, t, o);
        if (lane == 0) s_redB[wid][h] = t;
    }
    __syncthreads();
    #pragma unroll
    for (int h = 0; h < 8; ++h)
        csum[h] = s_redB[0][h] + s_redB[1][h] + s_redB[2][h] + s_redB[3][h];

    if (tid == 0) {
        #pragma unroll
        for (int h = 0; h < 8; ++h)
            g_part[(b * H_ + h) * NCHUNK + chunk] = make_float2(cmax[h], csum[h]);
    }

    // ---- store exp values to scratch (coalesced STG.32) ----
    const int j0 = chunk * ROWS + wid * WROWS + lane;
    #pragma unroll
    for (int h = 0; h < 8; ++h)
        g_scratch[(size_t)(b * H_ + h) * J_ + j0] = e[h];
}

// one warp per (b,h) row: combine 64 chunk partials (2 per lane) into scales
__global__ void __launch_bounds__(32)
cw_scales_kernel()
{
    const int x = blockIdx.x;          // b*H + h  (256 rows)
    const int c = threadIdx.x;         // lane

    float2 p0 = g_part[x * NCHUNK + c];
    float2 p1 = g_part[x * NCHUNK + 32 + c];
    float M = fmaxf(p0.x, p1.x);
    #pragma unroll
    for (int o = 16; o; o >>= 1) M = fmaxf(M, __shfl_xor_sync(0xffffffffu, M, o));
    float e0 = __expf(p0.x - M);
    float e1 = __expf(p1.x - M);
    float s = p0.y * e0 + p1.y * e1;
    #pragma unroll
    for (int o = 16; o; o >>= 1) s += __shfl_xor_sync(0xffffffffu, s, o);
    float inv = 1.f / s;
    g_scale[x * NCHUNK + c]      = e0 * inv;
    g_scale[x * NCHUNK + 32 + c] = e1 * inv;
}

// pure streaming rescale: 16 MB through, no smem, no shuffles
__global__ void __launch_bounds__(512)
cw_finalize_kernel(float* __restrict__ out)
{
    const int x = blockIdx.y;          // b*H + h  (256 rows)
    const int q = blockIdx.x;          // quarter of the row
    const int tid = threadIdx.x;       // 512 threads

    const int i = q * 512 + tid;       // float4 index in row (2048 total)
    const int c = i >> 5;              // 32 float4 per 128-float chunk
    const float sc = __ldg(g_scale + x * NCHUNK + c);

    const float4* src = (const float4*)(g_scratch + (size_t)x * J_);
    float4* dst = (float4*)(out + (size_t)x * J_);
    float4 v = src[i];
    dst[i] = make_float4(v.x * sc, v.y * sc, v.z * sc, v.w * sc);
}

extern "C" void kernel_launch(void* const* d_in, const int* in_sizes, int n_in,
                              void* d_out, int out_size)
{
    const float* memory    = (const float*)d_in[0];
    const float* keys      = (const float*)d_in[1];
    const float* strengths = (const float*)d_in[2];
    const float* mask      = (const float*)d_in[3];
    float* out = (float*)d_out;

    static bool attr_set = false;
    if (!attr_set) {
        cudaFuncSetAttribute(cw_main_kernel,
                             cudaFuncAttributeMaxDynamicSharedMemorySize,
                             4 * 2 * WBUF * (int)sizeof(float));
        attr_set = true;
    }

    cw_main_kernel<<<dim3(NCHUNK, B_), CTA_THREADS,
                     4 * 2 * WBUF * sizeof(float)>>>(memory, keys, strengths, mask);
    cw_scales_kernel<<<B_ * H_, 32>>>();
    cw_finalize_kernel<<<dim3(4, B_ * H_), 512>>>(out);
}

// round 14
// speedup vs baseline: 1.1025x; 1.1025x over previous
#include <cuda_runtime.h>
#include <cuda_bf16.h>
#include <math.h>

// Shapes: B=32, H=8, J=8192, K=128
#define B_ 32
#define H_ 8
#define J_ 8192
#define K_ 128
#define EPSV 1e-6f

#define CTA_THREADS 128
#define ROWS 256            // j rows per CTA
#define WROWS 64            // j rows per warp
#define NCHUNK 32           // j chunks per batch = J_/ROWS
#define KC 8                // k per stage (32B per row per stage)
#define NKC 16              // stages = K_/KC
#define PAD 12              // floats per staged row (8 data + 4 pad); conflict-free, 48B rows
#define WBUF (WROWS * PAD)  // 768 floats = 3 KB per warp buffer
// total dyn smem: 4 warps * 2 buffers * 3 KB = 24 KB

typedef unsigned long long ull;

// scratch: exp(sharp - chunk_max), 32*8*8192 f32 = 8 MB
__device__ float g_scratch[B_ * H_ * J_];
// per-(b,h,chunk) partials {max, sumexp}
__device__ float2 g_part[B_ * H_ * NCHUNK];
// per-(b,h,chunk) final softmax scale
__device__ float g_scale[B_ * H_ * NCHUNK];

#define FMA2(d, a, b, c) asm("fma.rn.f32x2 %0, %1, %2, %3;" : "=l"(d) : "l"(a), "l"(b), "l"(c))
#define MUL2(d, a, b)    asm("mul.rn.f32x2 %0, %1, %2;"     : "=l"(d) : "l"(a), "l"(b))
#define PACK2(d, lo, hi) asm("mov.b64 %0, {%1, %2};" : "=l"(d) : "f"(lo), "f"(hi))
#define UNPACK2(lo, hi, s) asm("mov.b64 {%0, %1}, %2;" : "=f"(lo), "=f"(hi) : "l"(s))

__device__ __forceinline__ void cp_async16(void* smem_dst, const void* gsrc) {
    unsigned saddr = (unsigned)__cvta_generic_to_shared(smem_dst);
    asm volatile("cp.async.cg.shared.global [%0], [%1], 16;" :: "r"(saddr), "l"(gsrc));
}

__global__ void __launch_bounds__(CTA_THREADS, 5)
cw_main_kernel(const float* __restrict__ memory,
               const float* __restrict__ keys,
               const float* __restrict__ strengths,
               const float* __restrict__ mask)
{
    extern __shared__ float sdata[];   // 4 warps * 2 * WBUF

    const int b = blockIdx.y;
    const int chunk = blockIdx.x;      // NCHUNK chunks of ROWS j
    const int tid = threadIdx.x;       // 128 threads
    const int lane = tid & 31;
    const int wid = tid >> 5;          // 4 warps

    __shared__ __align__(16) float s_w[K_ * H_];   // [k][h]
    __shared__ __align__(16) float s_m2[K_ * H_];  // [k][h]
    __shared__ float s_kn[H_];
    __shared__ float s_sps[H_];
    __shared__ float s_redA[4][8];
    __shared__ float s_redB[4][8];

    // ---- coefficient prep ----
    const float* mk = mask + b * (H_ * K_);
    const float* ky = keys + b * (H_ * K_);
    for (int i = tid; i < H_ * K_; i += CTA_THREADS) {
        int h = i >> 7;
        int k = i & 127;
        float m = mk[i];
        float kv = ky[i];
        float m2 = m * m;
        s_w[k * 8 + h]  = m2 * kv;
        s_m2[k * 8 + h] = m2;
    }
    // keys_norm: warp w handles heads w and w+4
    #pragma unroll
    for (int hh = 0; hh < 2; ++hh) {
        int h = wid + hh * 4;
        float s = 0.f;
        #pragma unroll
        for (int kk = 0; kk < 4; ++kk) {
            int k = lane + kk * 32;
            float v = mk[h * K_ + k] * ky[h * K_ + k];
            s += v * v;
        }
        #pragma unroll
        for (int o = 16; o; o >>= 1) s += __shfl_xor_sync(0xffffffffu, s, o);
        if (lane == 0) s_kn[h] = sqrtf(s);
    }
    if (tid < H_) {
        float x = strengths[b * H_ + tid];
        s_sps[tid] = (x > 20.f) ? x : log1pf(__expf(x));
    }

    // ---- per-warp staging ----
    // warp wid owns global rows [chunk*ROWS + wid*64, +64) and its own smem region
    float* wbase = sdata + wid * (2 * WBUF);
    const float* gw = memory + ((size_t)b * J_ + (size_t)chunk * ROWS + (size_t)wid * WROWS) * K_;

    // per stage per warp: 64 rows x 8 floats = 128 x 16B ops; 4 per lane
    #define WSTAGE(kc, buf)                                                       \
        {                                                                         \
            float* dbase = wbase + (buf) * WBUF;                                  \
            _Pragma("unroll")                                                     \
            for (int it = 0; it < 4; ++it) {                                      \
                int idx = it * 32 + lane;                                         \
                int row = idx >> 1;                                               \
                int seg = idx & 1;                                                \
                cp_async16(dbase + row * PAD + seg * 4,                           \
                           gw + (size_t)row * K_ + (kc) * KC + seg * 4);          \
            }                                                                     \
            asm volatile("cp.async.commit_group;");                               \
        }

    WSTAGE(0, 0);
    __syncthreads();   // coefficients visible to all warps

    const ulonglong2* w128 = (const ulonglong2*)s_w;   // [kg*2 + p]: heads 4p..4p+3
    const ulonglong2* q128 = (const ulonglong2*)s_m2;

    ull accP[2][4], accN[2][4];
    #pragma unroll
    for (int r = 0; r < 2; ++r)
        #pragma unroll
        for (int hp = 0; hp < 4; ++hp) { accP[r][hp] = 0ull; accN[r][hp] = 0ull; }

    const int i0 = lane * (PAD / 4);            // local row lane       (float4 units)
    const int i1 = (lane + 32) * (PAD / 4);     // local row lane+32

    #pragma unroll
    for (int kc = 0; kc < NKC; ++kc) {
        if (kc < NKC - 1) {
            WSTAGE(kc + 1, (kc + 1) & 1);
            asm volatile("cp.async.wait_group 1;");
        } else {
            asm volatile("cp.async.wait_group 0;");
        }
        __syncwarp();   // cross-lane visibility of staged data

        const float4* dp = (const float4*)(wbase + (kc & 1) * WBUF);
        #pragma unroll
        for (int k4 = 0; k4 < 2; ++k4) {
            float4 d0 = dp[i0 + k4];
            float4 d1 = dp[i1 + k4];
            float m0a[4] = {d0.x, d0.y, d0.z, d0.w};
            float m1a[4] = {d1.x, d1.y, d1.z, d1.w};
            #pragma unroll
            for (int kk = 0; kk < 4; ++kk) {
                const int kg = kc * KC + k4 * 4 + kk;
                ulonglong2 wA = w128[kg * 2 + 0];   // heads 0-3
                ulonglong2 wB = w128[kg * 2 + 1];   // heads 4-7
                ulonglong2 qA = q128[kg * 2 + 0];
                ulonglong2 qB = q128[kg * 2 + 1];
                {
                    float m = m0a[kk];
                    ull mm; PACK2(mm, m, m);
                    ull ms; MUL2(ms, mm, mm);
                    FMA2(accP[0][0], wA.x, mm, accP[0][0]);
                    FMA2(accN[0][0], qA.x, ms, accN[0][0]);
                    FMA2(accP[0][1], wA.y, mm, accP[0][1]);
                    FMA2(accN[0][1], qA.y, ms, accN[0][1]);
                    FMA2(accP[0][2], wB.x, mm, accP[0][2]);
                    FMA2(accN[0][2], qB.x, ms, accN[0][2]);
                    FMA2(accP[0][3], wB.y, mm, accP[0][3]);
                    FMA2(accN[0][3], qB.y, ms, accN[0][3]);
                }
                {
                    float m = m1a[kk];
                    ull mm; PACK2(mm, m, m);
                    ull ms; MUL2(ms, mm, mm);
                    FMA2(accP[1][0], wA.x, mm, accP[1][0]);
                    FMA2(accN[1][0], qA.x, ms, accN[1][0]);
                    FMA2(accP[1][1], wA.y, mm, accP[1][1]);
                    FMA2(accN[1][1], qA.y, ms, accN[1][1]);
                    FMA2(accP[1][2], wB.x, mm, accP[1][2]);
                    FMA2(accN[1][2], qB.x, ms, accN[1][2]);
                    FMA2(accP[1][3], wB.y, mm, accP[1][3]);
                    FMA2(accN[1][3], qB.y, ms, accN[1][3]);
                }
            }
        }
        __syncwarp();   // all lanes done reading buffer before next overwrite
    }

    // ---- epilogue: sharp = proj/(kn*sqrt(nrm2)+eps) * sps ----
    float sharp[2][8];
    #pragma unroll
    for (int r = 0; r < 2; ++r) {
        #pragma unroll
        for (int hp = 0; hp < 4; ++hp) {
            float p0, p1, n0, n1;
            UNPACK2(p0, p1, accP[r][hp]);
            UNPACK2(n0, n1, accN[r][hp]);
            const int h0 = hp * 2, h1 = hp * 2 + 1;
            sharp[r][h0] = p0 / (s_kn[h0] * sqrtf(n0) + EPSV) * s_sps[h0];
            sharp[r][h1] = p1 / (s_kn[h1] * sqrtf(n1) + EPSV) * s_sps[h1];
        }
    }

    // ---- chunk-level softmax partials ----
    float cmax[8];
    #pragma unroll
    for (int h = 0; h < 8; ++h) {
        float t = fmaxf(sharp[0][h], sharp[1][h]);
        #pragma unroll
        for (int o = 16; o; o >>= 1) t = fmaxf(t, __shfl_xor_sync(0xffffffffu, t, o));
        if (lane == 0) s_redA[wid][h] = t;
    }
    __syncthreads();
    #pragma unroll
    for (int h = 0; h < 8; ++h)
        cmax[h] = fmaxf(fmaxf(s_redA[0][h], s_redA[1][h]),
                        fmaxf(s_redA[2][h], s_redA[3][h]));

    float e[2][8];
    float csum[8];
    #pragma unroll
    for (int h = 0; h < 8; ++h) {
        float t0 = __expf(sharp[0][h] - cmax[h]);
        float t1 = __expf(sharp[1][h] - cmax[h]);
        e[0][h] = t0; e[1][h] = t1;
        float t = t0 + t1;
        #pragma unroll
        for (int o = 16; o; o >>= 1) t += __shfl_xor_sync(0xffffffffu, t, o);
        if (lane == 0) s_redB[wid][h] = t;
    }
    __syncthreads();
    #pragma unroll
    for (int h = 0; h < 8; ++h)
        csum[h] = s_redB[0][h] + s_redB[1][h] + s_redB[2][h] + s_redB[3][h];

    if (tid == 0) {
        #pragma unroll
        for (int h = 0; h < 8; ++h)
            g_part[(b * H_ + h) * NCHUNK + chunk] = make_float2(cmax[h], csum[h]);
    }

    // ---- store exp values to scratch (coalesced STG.32, rows +0 / +32 of warp tile) ----
    const int j0 = chunk * ROWS + wid * WROWS + lane;
    #pragma unroll
    for (int h = 0; h < 8; ++h) {
        float* dst = g_scratch + (size_t)(b * H_ + h) * J_ + j0;
        dst[0]  = e[0][h];
        dst[32] = e[1][h];
    }
}

// one warp per (b,h) row: combine 32 chunk partials into per-chunk scales
__global__ void __launch_bounds__(32)
cw_scales_kernel()
{
    const int x = blockIdx.x;          // b*H + h  (256 rows)
    const int c = threadIdx.x;         // 32 chunks

    float2 p = g_part[x * NCHUNK + c];
    float M = p.x;
    #pragma unroll
    for (int o = 16; o; o >>= 1) M = fmaxf(M, __shfl_xor_sync(0xffffffffu, M, o));
    float ex = __expf(p.x - M);
    float s = p.y * ex;
    #pragma unroll
    for (int o = 16; o; o >>= 1) s += __shfl_xor_sync(0xffffffffu, s, o);
    g_scale[x * NCHUNK + c] = ex / s;
}

// pure streaming rescale: 16 MB through, no smem, no shuffles
__global__ void __launch_bounds__(512)
cw_finalize_kernel(float* __restrict__ out)
{
    const int x = blockIdx.y;          // b*H + h  (256 rows)
    const int q = blockIdx.x;          // quarter of the row
    const int tid = threadIdx.x;       // 512 threads

    const int i = q * 512 + tid;       // float4 index in row (2048 total)
    const int c = i >> 6;              // 64 float4 per 256-float chunk
    const float sc = __ldg(g_scale + x * NCHUNK + c);

    const float4* src = (const float4*)(g_scratch + (size_t)x * J_);
    float4* dst = (float4*)(out + (size_t)x * J_);
    float4 v = src[i];
    dst[i] = make_float4(v.x * sc, v.y * sc, v.z * sc, v.w * sc);
}

extern "C" void kernel_launch(void* const* d_in, const int* in_sizes, int n_in,
                              void* d_out, int out_size)
{
    const float* memory    = (const float*)d_in[0];
    const float* keys      = (const float*)d_in[1];
    const float* strengths = (const float*)d_in[2];
    const float* mask      = (const float*)d_in[3];
    float* out = (float*)d_out;

    static bool attr_set = false;
    if (!attr_set) {
        cudaFuncSetAttribute(cw_main_kernel,
                             cudaFuncAttributeMaxDynamicSharedMemorySize,
                             4 * 2 * WBUF * (int)sizeof(float));
        attr_set = true;
    }

    cw_main_kernel<<<dim3(NCHUNK, B_), CTA_THREADS,
                     4 * 2 * WBUF * sizeof(float)>>>(memory, keys, strengths, mask);
    cw_scales_kernel<<<B_ * H_, 32>>>();
    cw_finalize_kernel<<<dim3(4, B_ * H_), 512>>>(out);
}

// round 15
// speedup vs baseline: 1.1453x; 1.0388x over previous
#include <cuda_runtime.h>
#include <cuda_bf16.h>
#include <math.h>

// Shapes: B=32, H=8, J=8192, K=128
#define B_ 32
#define H_ 8
#define J_ 8192
#define K_ 128
#define EPSV 1e-6f

#define CTA_THREADS 128
#define ROWS 256            // j rows per CTA
#define WROWS 64            // j rows per warp
#define NCHUNK 32           // j chunks per batch = J_/ROWS
#define KC 16               // k per stage (64B per row per stage)
#define NKC 8               // stages = K_/KC
#define PAD 20              // floats per staged row (16 data + 4 pad); conflict-free
#define WBUF (WROWS * PAD)  // 1280 floats = 5 KB per warp buffer
// total dyn smem: 4 warps * 2 buffers * 5 KB = 40 KB

typedef unsigned long long ull;

// scratch: exp(sharp - chunk_max), 32*8*8192 f32 = 8 MB
__device__ float g_scratch[B_ * H_ * J_];
// per-(b,h,chunk) partials {max, sumexp}
__device__ float2 g_part[B_ * H_ * NCHUNK];

#define FMA2(d, a, b, c) asm("fma.rn.f32x2 %0, %1, %2, %3;" : "=l"(d) : "l"(a), "l"(b), "l"(c))
#define MUL2(d, a, b)    asm("mul.rn.f32x2 %0, %1, %2;"     : "=l"(d) : "l"(a), "l"(b))
#define PACK2(d, lo, hi) asm("mov.b64 %0, {%1, %2};" : "=l"(d) : "f"(lo), "f"(hi))
#define UNPACK2(lo, hi, s) asm("mov.b64 {%0, %1}, %2;" : "=f"(lo), "=f"(hi) : "l"(s))

__device__ __forceinline__ void cp_async16(void* smem_dst, const void* gsrc) {
    unsigned saddr = (unsigned)__cvta_generic_to_shared(smem_dst);
    asm volatile("cp.async.cg.shared.global [%0], [%1], 16;" :: "r"(saddr), "l"(gsrc));
}

__global__ void __launch_bounds__(CTA_THREADS, 4)
cw_main_kernel(const float* __restrict__ memory,
               const float* __restrict__ keys,
               const float* __restrict__ strengths,
               const float* __restrict__ mask)
{
    extern __shared__ float sdata[];   // 4 warps * 2 * WBUF

    const int b = blockIdx.y;
    const int chunk = blockIdx.x;      // NCHUNK chunks of ROWS j
    const int tid = threadIdx.x;       // 128 threads
    const int lane = tid & 31;
    const int wid = tid >> 5;          // 4 warps

    __shared__ __align__(16) float s_w[K_ * H_];   // [k][h]
    __shared__ __align__(16) float s_m2[K_ * H_];  // [k][h]
    __shared__ float s_kn[H_];
    __shared__ float s_sps[H_];
    __shared__ float s_redA[4][8];
    __shared__ float s_redB[4][8];

    // ---- coefficient prep ----
    const float* mk = mask + b * (H_ * K_);
    const float* ky = keys + b * (H_ * K_);
    for (int i = tid; i < H_ * K_; i += CTA_THREADS) {
        int h = i >> 7;
        int k = i & 127;
        float m = mk[i];
        float kv = ky[i];
        float m2 = m * m;
        s_w[k * 8 + h]  = m2 * kv;
        s_m2[k * 8 + h] = m2;
    }
    // keys_norm: warp w handles heads w and w+4
    #pragma unroll
    for (int hh = 0; hh < 2; ++hh) {
        int h = wid + hh * 4;
        float s = 0.f;
        #pragma unroll
        for (int kk = 0; kk < 4; ++kk) {
            int k = lane + kk * 32;
            float v = mk[h * K_ + k] * ky[h * K_ + k];
            s += v * v;
        }
        #pragma unroll
        for (int o = 16; o; o >>= 1) s += __shfl_xor_sync(0xffffffffu, s, o);
        if (lane == 0) s_kn[h] = sqrtf(s);
    }
    if (tid < H_) {
        float x = strengths[b * H_ + tid];
        s_sps[tid] = (x > 20.f) ? x : log1pf(__expf(x));
    }

    // ---- per-warp staging ----
    float* wbase = sdata + wid * (2 * WBUF);
    const float* gw = memory + ((size_t)b * J_ + (size_t)chunk * ROWS + (size_t)wid * WROWS) * K_;

    // per stage per warp: 64 rows x 16 floats = 256 x 16B ops; 8 per lane
    #define WSTAGE(kc, buf)                                                       \
        {                                                                         \
            float* dbase = wbase + (buf) * WBUF;                                  \
            _Pragma("unroll")                                                     \
            for (int it = 0; it < 8; ++it) {                                      \
                int idx = it * 32 + lane;                                         \
                int row = idx >> 2;                                               \
                int seg = idx & 3;                                                \
                cp_async16(dbase + row * PAD + seg * 4,                           \
                           gw + (size_t)row * K_ + (kc) * KC + seg * 4);          \
            }                                                                     \
            asm volatile("cp.async.commit_group;");                               \
        }

    WSTAGE(0, 0);
    __syncthreads();   // coefficients visible to all warps

    const ulonglong2* w128 = (const ulonglong2*)s_w;   // [kg*2 + p]: heads 4p..4p+3
    const ulonglong2* q128 = (const ulonglong2*)s_m2;

    ull accP[2][4], accN[2][4];
    #pragma unroll
    for (int r = 0; r < 2; ++r)
        #pragma unroll
        for (int hp = 0; hp < 4; ++hp) { accP[r][hp] = 0ull; accN[r][hp] = 0ull; }

    const int i0 = lane * (PAD / 4);            // local row lane       (float4 units)
    const int i1 = (lane + 32) * (PAD / 4);     // local row lane+32

    #pragma unroll
    for (int kc = 0; kc < NKC; ++kc) {
        if (kc < NKC - 1) {
            WSTAGE(kc + 1, (kc + 1) & 1);
            asm volatile("cp.async.wait_group 1;");
        } else {
            asm volatile("cp.async.wait_group 0;");
        }
        __syncwarp();   // cross-lane visibility of staged data

        const float4* dp = (const float4*)(wbase + (kc & 1) * WBUF);
        #pragma unroll
        for (int k4 = 0; k4 < 4; ++k4) {
            float4 d0 = dp[i0 + k4];
            float4 d1 = dp[i1 + k4];
            float m0a[4] = {d0.x, d0.y, d0.z, d0.w};
            float m1a[4] = {d1.x, d1.y, d1.z, d1.w};
            #pragma unroll
            for (int kk = 0; kk < 4; ++kk) {
                const int kg = kc * KC + k4 * 4 + kk;
                ulonglong2 wA = w128[kg * 2 + 0];   // heads 0-3
                ulonglong2 wB = w128[kg * 2 + 1];   // heads 4-7
                ulonglong2 qA = q128[kg * 2 + 0];
                ulonglong2 qB = q128[kg * 2 + 1];
                {
                    float m = m0a[kk];
                    ull mm; PACK2(mm, m, m);
                    ull ms; MUL2(ms, mm, mm);
                    FMA2(accP[0][0], wA.x, mm, accP[0][0]);
                    FMA2(accN[0][0], qA.x, ms, accN[0][0]);
                    FMA2(accP[0][1], wA.y, mm, accP[0][1]);
                    FMA2(accN[0][1], qA.y, ms, accN[0][1]);
                    FMA2(accP[0][2], wB.x, mm, accP[0][2]);
                    FMA2(accN[0][2], qB.x, ms, accN[0][2]);
                    FMA2(accP[0][3], wB.y, mm, accP[0][3]);
                    FMA2(accN[0][3], qB.y, ms, accN[0][3]);
                }
                {
                    float m = m1a[kk];
                    ull mm; PACK2(mm, m, m);
                    ull ms; MUL2(ms, mm, mm);
                    FMA2(accP[1][0], wA.x, mm, accP[1][0]);
                    FMA2(accN[1][0], qA.x, ms, accN[1][0]);
                    FMA2(accP[1][1], wA.y, mm, accP[1][1]);
                    FMA2(accN[1][1], qA.y, ms, accN[1][1]);
                    FMA2(accP[1][2], wB.x, mm, accP[1][2]);
                    FMA2(accN[1][2], qB.x, ms, accN[1][2]);
                    FMA2(accP[1][3], wB.y, mm, accP[1][3]);
                    FMA2(accN[1][3], qB.y, ms, accN[1][3]);
                }
            }
        }
        __syncwarp();   // all lanes done reading buffer before next overwrite
    }

    // ---- epilogue: sharp = proj/(kn*sqrt(nrm2)+eps) * sps ----
    float sharp[2][8];
    #pragma unroll
    for (int r = 0; r < 2; ++r) {
        #pragma unroll
        for (int hp = 0; hp < 4; ++hp) {
            float p0, p1, n0, n1;
            UNPACK2(p0, p1, accP[r][hp]);
            UNPACK2(n0, n1, accN[r][hp]);
            const int h0 = hp * 2, h1 = hp * 2 + 1;
            sharp[r][h0] = p0 / (s_kn[h0] * sqrtf(n0) + EPSV) * s_sps[h0];
            sharp[r][h1] = p1 / (s_kn[h1] * sqrtf(n1) + EPSV) * s_sps[h1];
        }
    }

    // ---- chunk-level softmax partials ----
    float cmax[8];
    #pragma unroll
    for (int h = 0; h < 8; ++h) {
        float t = fmaxf(sharp[0][h], sharp[1][h]);
        #pragma unroll
        for (int o = 16; o; o >>= 1) t = fmaxf(t, __shfl_xor_sync(0xffffffffu, t, o));
        if (lane == 0) s_redA[wid][h] = t;
    }
    __syncthreads();
    #pragma unroll
    for (int h = 0; h < 8; ++h)
        cmax[h] = fmaxf(fmaxf(s_redA[0][h], s_redA[1][h]),
                        fmaxf(s_redA[2][h], s_redA[3][h]));

    float e[2][8];
    float csum[8];
    #pragma unroll
    for (int h = 0; h < 8; ++h) {
        float t0 = __expf(sharp[0][h] - cmax[h]);
        float t1 = __expf(sharp[1][h] - cmax[h]);
        e[0][h] = t0; e[1][h] = t1;
        float t = t0 + t1;
        #pragma unroll
        for (int o = 16; o; o >>= 1) t += __shfl_xor_sync(0xffffffffu, t, o);
        if (lane == 0) s_redB[wid][h] = t;
    }
    __syncthreads();
    #pragma unroll
    for (int h = 0; h < 8; ++h)
        csum[h] = s_redB[0][h] + s_redB[1][h] + s_redB[2][h] + s_redB[3][h];

    if (tid == 0) {
        #pragma unroll
        for (int h = 0; h < 8; ++h)
            g_part[(b * H_ + h) * NCHUNK + chunk] = make_float2(cmax[h], csum[h]);
    }

    // ---- store exp values to scratch (coalesced STG.32, rows +0 / +32 of warp tile) ----
    const int j0 = chunk * ROWS + wid * WROWS + lane;
    #pragma unroll
    for (int h = 0; h < 8; ++h) {
        float* dst = g_scratch + (size_t)(b * H_ + h) * J_ + j0;
        dst[0]  = e[0][h];
        dst[32] = e[1][h];
    }
}

// fused scales + streaming rescale: warp 0 computes the 32 chunk scales,
// then the whole 1024-thread block streams half a row (16 KB).
__global__ void __launch_bounds__(1024)
cw_finalize_kernel(float* __restrict__ out)
{
    const int x = blockIdx.y;          // b*H + h  (256 rows)
    const int half = blockIdx.x;       // 0 or 1: half of the row
    const int tid = threadIdx.x;       // 1024 threads

    __shared__ float s_scale[NCHUNK];

    if (tid < 32) {
        float2 p = g_part[x * NCHUNK + tid];
        float M = p.x;
        #pragma unroll
        for (int o = 16; o; o >>= 1) M = fmaxf(M, __shfl_xor_sync(0xffffffffu, M, o));
        float ex = __expf(p.x - M);
        float s = p.y * ex;
        #pragma unroll
        for (int o = 16; o; o >>= 1) s += __shfl_xor_sync(0xffffffffu, s, o);
        s_scale[tid] = ex / s;
    }
    __syncthreads();

    const int i = half * 1024 + tid;   // float4 index in row (2048 total)
    const int c = i >> 6;              // 64 float4 per 256-float chunk
    const float sc = s_scale[c];

    const float4* src = (const float4*)(g_scratch + (size_t)x * J_);
    float4* dst = (float4*)(out + (size_t)x * J_);
    float4 v = src[i];
    dst[i] = make_float4(v.x * sc, v.y * sc, v.z * sc, v.w * sc);
}

extern "C" void kernel_launch(void* const* d_in, const int* in_sizes, int n_in,
                              void* d_out, int out_size)
{
    const float* memory    = (const float*)d_in[0];
    const float* keys      = (const float*)d_in[1];
    const float* strengths = (const float*)d_in[2];
    const float* mask      = (const float*)d_in[3];
    float* out = (float*)d_out;

    static bool attr_set = false;
    if (!attr_set) {
        cudaFuncSetAttribute(cw_main_kernel,
                             cudaFuncAttributeMaxDynamicSharedMemorySize,
                             4 * 2 * WBUF * (int)sizeof(float));
        attr_set = true;
    }

    cw_main_kernel<<<dim3(NCHUNK, B_), CTA_THREADS,
                     4 * 2 * WBUF * sizeof(float)>>>(memory, keys, strengths, mask);
    cw_finalize_kernel<<<dim3(2, B_ * H_), 1024>>>(out);
}

// round 16
// speedup vs baseline: 1.1524x; 1.0062x over previous
#include <cuda_runtime.h>
#include <cuda_bf16.h>
#include <math.h>

// Shapes: B=32, H=8, J=8192, K=128
#define B_ 32
#define H_ 8
#define J_ 8192
#define K_ 128
#define EPSV 1e-6f

#define CTA_THREADS 128
#define ROWS 256            // j rows per CTA
#define WROWS 64            // j rows per warp
#define NCHUNK 32           // j chunks per batch = J_/ROWS
#define KC 8                // k per stage (32B per row per stage)
#define NKC 16              // stages = K_/KC
#define PAD 12              // floats per staged row (8 data + 4 pad); conflict-free
#define WBUF (WROWS * PAD)  // 768 floats = 3 KB per warp buffer
#define NBUF 3              // prefetch depth 2 (3-stage ring)
// total dyn smem: 4 warps * 3 buffers * 3 KB = 36 KB

typedef unsigned long long ull;

// scratch: exp(sharp - chunk_max), 32*8*8192 f32 = 8 MB
__device__ float g_scratch[B_ * H_ * J_];
// per-(b,h,chunk) partials {max, sumexp}
__device__ float2 g_part[B_ * H_ * NCHUNK];

#define FMA2(d, a, b, c) asm("fma.rn.f32x2 %0, %1, %2, %3;" : "=l"(d) : "l"(a), "l"(b), "l"(c))
#define MUL2(d, a, b)    asm("mul.rn.f32x2 %0, %1, %2;"     : "=l"(d) : "l"(a), "l"(b))
#define PACK2(d, lo, hi) asm("mov.b64 %0, {%1, %2};" : "=l"(d) : "f"(lo), "f"(hi))
#define UNPACK2(lo, hi, s) asm("mov.b64 {%0, %1}, %2;" : "=f"(lo), "=f"(hi) : "l"(s))

__device__ __forceinline__ void cp_async16(void* smem_dst, const void* gsrc) {
    unsigned saddr = (unsigned)__cvta_generic_to_shared(smem_dst);
    asm volatile("cp.async.cg.shared.global [%0], [%1], 16;" :: "r"(saddr), "l"(gsrc));
}

__global__ void __launch_bounds__(CTA_THREADS, 4)
cw_main_kernel(const float* __restrict__ memory,
               const float* __restrict__ keys,
               const float* __restrict__ strengths,
               const float* __restrict__ mask)
{
    extern __shared__ float sdata[];   // 4 warps * NBUF * WBUF

    const int b = blockIdx.y;
    const int chunk = blockIdx.x;      // NCHUNK chunks of ROWS j
    const int tid = threadIdx.x;       // 128 threads
    const int lane = tid & 31;
    const int wid = tid >> 5;          // 4 warps

    __shared__ __align__(16) float s_w[K_ * H_];   // [k][h]
    __shared__ __align__(16) float s_m2[K_ * H_];  // [k][h]
    __shared__ float s_kn[H_];
    __shared__ float s_sps[H_];
    __shared__ float s_redA[4][8];
    __shared__ float s_redB[4][8];

    // ---- coefficient prep ----
    const float* mk = mask + b * (H_ * K_);
    const float* ky = keys + b * (H_ * K_);
    for (int i = tid; i < H_ * K_; i += CTA_THREADS) {
        int h = i >> 7;
        int k = i & 127;
        float m = mk[i];
        float kv = ky[i];
        float m2 = m * m;
        s_w[k * 8 + h]  = m2 * kv;
        s_m2[k * 8 + h] = m2;
    }
    // keys_norm: warp w handles heads w and w+4
    #pragma unroll
    for (int hh = 0; hh < 2; ++hh) {
        int h = wid + hh * 4;
        float s = 0.f;
        #pragma unroll
        for (int kk = 0; kk < 4; ++kk) {
            int k = lane + kk * 32;
            float v = mk[h * K_ + k] * ky[h * K_ + k];
            s += v * v;
        }
        #pragma unroll
        for (int o = 16; o; o >>= 1) s += __shfl_xor_sync(0xffffffffu, s, o);
        if (lane == 0) s_kn[h] = sqrtf(s);
    }
    if (tid < H_) {
        float x = strengths[b * H_ + tid];
        s_sps[tid] = (x > 20.f) ? x : log1pf(__expf(x));
    }

    // ---- per-warp staging (3-stage ring, prefetch depth 2) ----
    float* wbase = sdata + wid * (NBUF * WBUF);
    const float* gw = memory + ((size_t)b * J_ + (size_t)chunk * ROWS + (size_t)wid * WROWS) * K_;

    // per stage per warp: 64 rows x 8 floats = 128 x 16B ops; 4 per lane
    #define WSTAGE(kc, buf)                                                       \
        {                                                                         \
            float* dbase = wbase + (buf) * WBUF;                                  \
            _Pragma("unroll")                                                     \
            for (int it = 0; it < 4; ++it) {                                      \
                int idx = it * 32 + lane;                                         \
                int row = idx >> 1;                                               \
                int seg = idx & 1;                                                \
                cp_async16(dbase + row * PAD + seg * 4,                           \
                           gw + (size_t)row * K_ + (kc) * KC + seg * 4);          \
            }                                                                     \
            asm volatile("cp.async.commit_group;");                               \
        }

    WSTAGE(0, 0);
    WSTAGE(1, 1);
    __syncthreads();   // coefficients visible to all warps

    const ulonglong2* w128 = (const ulonglong2*)s_w;   // [kg*2 + p]: heads 4p..4p+3
    const ulonglong2* q128 = (const ulonglong2*)s_m2;

    ull accP[2][4], accN[2][4];
    #pragma unroll
    for (int r = 0; r < 2; ++r)
        #pragma unroll
        for (int hp = 0; hp < 4; ++hp) { accP[r][hp] = 0ull; accN[r][hp] = 0ull; }

    const int i0 = lane * (PAD / 4);            // local row lane       (float4 units)
    const int i1 = (lane + 32) * (PAD / 4);     // local row lane+32

    #pragma unroll
    for (int kc = 0; kc < NKC; ++kc) {
        if (kc < NKC - 2) {
            WSTAGE(kc + 2, (kc + 2) % NBUF);
            asm volatile("cp.async.wait_group 2;");
        } else if (kc == NKC - 2) {
            asm volatile("cp.async.wait_group 1;");
        } else {
            asm volatile("cp.async.wait_group 0;");
        }
        __syncwarp();   // cross-lane visibility of staged data

        const float4* dp = (const float4*)(wbase + (kc % NBUF) * WBUF);
        #pragma unroll
        for (int k4 = 0; k4 < 2; ++k4) {
            float4 d0 = dp[i0 + k4];
            float4 d1 = dp[i1 + k4];
            float m0a[4] = {d0.x, d0.y, d0.z, d0.w};
            float m1a[4] = {d1.x, d1.y, d1.z, d1.w};
            #pragma unroll
            for (int kk = 0; kk < 4; ++kk) {
                const int kg = kc * KC + k4 * 4 + kk;
                ulonglong2 wA = w128[kg * 2 + 0];   // heads 0-3
                ulonglong2 wB = w128[kg * 2 + 1];   // heads 4-7
                ulonglong2 qA = q128[kg * 2 + 0];
                ulonglong2 qB = q128[kg * 2 + 1];
                {
                    float m = m0a[kk];
                    ull mm; PACK2(mm, m, m);
                    ull ms; MUL2(ms, mm, mm);
                    FMA2(accP[0][0], wA.x, mm, accP[0][0]);
                    FMA2(accN[0][0], qA.x, ms, accN[0][0]);
                    FMA2(accP[0][1], wA.y, mm, accP[0][1]);
                    FMA2(accN[0][1], qA.y, ms, accN[0][1]);
                    FMA2(accP[0][2], wB.x, mm, accP[0][2]);
                    FMA2(accN[0][2], qB.x, ms, accN[0][2]);
                    FMA2(accP[0][3], wB.y, mm, accP[0][3]);
                    FMA2(accN[0][3], qB.y, ms, accN[0][3]);
                }
                {
                    float m = m1a[kk];
                    ull mm; PACK2(mm, m, m);
                    ull ms; MUL2(ms, mm, mm);
                    FMA2(accP[1][0], wA.x, mm, accP[1][0]);
                    FMA2(accN[1][0], qA.x, ms, accN[1][0]);
                    FMA2(accP[1][1], wA.y, mm, accP[1][1]);
                    FMA2(accN[1][1], qA.y, ms, accN[1][1]);
                    FMA2(accP[1][2], wB.x, mm, accP[1][2]);
                    FMA2(accN[1][2], qB.x, ms, accN[1][2]);
                    FMA2(accP[1][3], wB.y, mm, accP[1][3]);
                    FMA2(accN[1][3], qB.y, ms, accN[1][3]);
                }
            }
        }
        __syncwarp();   // all lanes done reading this buffer
    }

    // ---- epilogue: sharp = proj/(kn*sqrt(nrm2)+eps) * sps ----
    float sharp[2][8];
    #pragma unroll
    for (int r = 0; r < 2; ++r) {
        #pragma unroll
        for (int hp = 0; hp < 4; ++hp) {
            float p0, p1, n0, n1;
            UNPACK2(p0, p1, accP[r][hp]);
            UNPACK2(n0, n1, accN[r][hp]);
            const int h0 = hp * 2, h1 = hp * 2 + 1;
            sharp[r][h0] = p0 / (s_kn[h0] * sqrtf(n0) + EPSV) * s_sps[h0];
            sharp[r][h1] = p1 / (s_kn[h1] * sqrtf(n1) + EPSV) * s_sps[h1];
        }
    }

    // ---- chunk-level softmax partials ----
    float cmax[8];
    #pragma unroll
    for (int h = 0; h < 8; ++h) {
        float t = fmaxf(sharp[0][h], sharp[1][h]);
        #pragma unroll
        for (int o = 16; o; o >>= 1) t = fmaxf(t, __shfl_xor_sync(0xffffffffu, t, o));
        if (lane == 0) s_redA[wid][h] = t;
    }
    __syncthreads();
    #pragma unroll
    for (int h = 0; h < 8; ++h)
        cmax[h] = fmaxf(fmaxf(s_redA[0][h], s_redA[1][h]),
                        fmaxf(s_redA[2][h], s_redA[3][h]));

    float e[2][8];
    float csum[8];
    #pragma unroll
    for (int h = 0; h < 8; ++h) {
        float t0 = __expf(sharp[0][h] - cmax[h]);
        float t1 = __expf(sharp[1][h] - cmax[h]);
        e[0][h] = t0; e[1][h] = t1;
        float t = t0 + t1;
        #pragma unroll
        for (int o = 16; o; o >>= 1) t += __shfl_xor_sync(0xffffffffu, t, o);
        if (lane == 0) s_redB[wid][h] = t;
    }
    __syncthreads();
    #pragma unroll
    for (int h = 0; h < 8; ++h)
        csum[h] = s_redB[0][h] + s_redB[1][h] + s_redB[2][h] + s_redB[3][h];

    if (tid == 0) {
        #pragma unroll
        for (int h = 0; h < 8; ++h)
            g_part[(b * H_ + h) * NCHUNK + chunk] = make_float2(cmax[h], csum[h]);
    }

    // ---- store exp values to scratch (coalesced STG.32) ----
    const int j0 = chunk * ROWS + wid * WROWS + lane;
    #pragma unroll
    for (int h = 0; h < 8; ++h) {
        float* dst = g_scratch + (size_t)(b * H_ + h) * J_ + j0;
        dst[0]  = e[0][h];
        dst[32] = e[1][h];
    }
}

// fused scales + streaming rescale: one block per (b,h) row.
// Warp 0 computes the 32 chunk scales; then 512 threads stream the whole
// row, 4 float4 per thread with batched loads (MLP=4).
__global__ void __launch_bounds__(512)
cw_finalize_kernel(float* __restrict__ out)
{
    const int x = blockIdx.x;          // b*H + h  (256 rows)
    const int tid = threadIdx.x;       // 512 threads

    __shared__ float s_scale[NCHUNK];

    if (tid < 32) {
        float2 p = g_part[x * NCHUNK + tid];
        float M = p.x;
        #pragma unroll
        for (int o = 16; o; o >>= 1) M = fmaxf(M, __shfl_xor_sync(0xffffffffu, M, o));
        float ex = __expf(p.x - M);
        float s = p.y * ex;
        #pragma unroll
        for (int o = 16; o; o >>= 1) s += __shfl_xor_sync(0xffffffffu, s, o);
        s_scale[tid] = ex / s;
    }
    __syncthreads();

    const float4* src = (const float4*)(g_scratch + (size_t)x * J_);
    float4* dst = (float4*)(out + (size_t)x * J_);

    // 2048 float4 per row; thread handles i = tid + 512*u, u=0..3 (batched loads)
    float4 v[4];
    #pragma unroll
    for (int u = 0; u < 4; ++u) v[u] = src[tid + 512 * u];
    #pragma unroll
    for (int u = 0; u < 4; ++u) {
        const int i = tid + 512 * u;
        const float sc = s_scale[i >> 6];      // 64 float4 per 256-float chunk
        dst[i] = make_float4(v[u].x * sc, v[u].y * sc, v[u].z * sc, v[u].w * sc);
    }
}

extern "C" void kernel_launch(void* const* d_in, const int* in_sizes, int n_in,
                              void* d_out, int out_size)
{
    const float* memory    = (const float*)d_in[0];
    const float* keys      = (const float*)d_in[1];
    const float* strengths = (const float*)d_in[2];
    const float* mask      = (const float*)d_in[3];
    float* out = (float*)d_out;

    static bool attr_set = false;
    if (!attr_set) {
        cudaFuncSetAttribute(cw_main_kernel,
                             cudaFuncAttributeMaxDynamicSharedMemorySize,
                             4 * NBUF * WBUF * (int)sizeof(float));
        attr_set = true;
    }

    cw_main_kernel<<<dim3(NCHUNK, B_), CTA_THREADS,
                     4 * NBUF * WBUF * sizeof(float)>>>(memory, keys, strengths, mask);
    cw_finalize_kernel<<<B_ * H_, 512>>>(out);
}